// round 1
// baseline (speedup 1.0000x reference)
#include <cuda_runtime.h>

#define N_USER 50000
#define N_ITEM 100000
#define NTOT   150000
#define D      64
#define NLAY   3
#define NNZ    2400000
#define BATCH  1024

// ---------------- scratch (static device globals; no allocation) ----------------
__device__ int   g_rowptr[NTOT + 1];
__device__ int   g_cnt[NTOT];
__device__ int   g_fill[NTOT];
__device__ int   g_cols[NNZ];
__device__ float g_vals[NNZ];
__device__ float g_E[2][(size_t)NTOT * D];          // ping-pong unnormalized embeddings
__device__ float g_allE[(size_t)NTOT * 4 * D];      // concat [E0 | n1 | n2 | n3], row stride 256
__device__ float g_umlp[BATCH * D];
__device__ int   g_winner[N_USER];

// ---------------- f32x2 helpers (packed dual-FMA, sm_100+) ----------------
__device__ __forceinline__ unsigned long long pack_dup(float a) {
    unsigned long long r;
    asm("mov.b64 %0, {%1, %1};" : "=l"(r) : "f"(a));
    return r;
}
__device__ __forceinline__ unsigned long long pack2(float x, float y) {
    unsigned long long r;
    asm("mov.b64 %0, {%1, %2};" : "=l"(r) : "f"(x), "f"(y));
    return r;
}
__device__ __forceinline__ float2 unpack2(unsigned long long v) {
    float2 r;
    asm("mov.b64 {%0, %1}, %2;" : "=f"(r.x), "=f"(r.y) : "l"(v));
    return r;
}
__device__ __forceinline__ unsigned long long ffma2(unsigned long long a,
                                                    unsigned long long b,
                                                    unsigned long long c) {
    unsigned long long d;
    asm("fma.rn.f32x2 %0, %1, %2, %3;" : "=l"(d) : "l"(a), "l"(b), "l"(c));
    return d;
}

// ---------------- CSR build ----------------
__global__ void zero_kernel() {
    int i = blockIdx.x * blockDim.x + threadIdx.x;
    if (i < NTOT) { g_cnt[i] = 0; g_fill[i] = 0; }
    if (i < N_USER) g_winner[i] = -1;
}

__global__ void hist_kernel(const int* __restrict__ lap_row) {
    int e = blockIdx.x * blockDim.x + threadIdx.x;
    if (e < NNZ) atomicAdd(&g_cnt[lap_row[e]], 1);
}

__global__ void scan_kernel() {
    __shared__ int wsum[32];
    __shared__ int carryS;
    int t = threadIdx.x, lane = t & 31, wid = t >> 5;
    if (t == 0) { carryS = 0; g_rowptr[0] = 0; }
    __syncthreads();
    for (int base = 0; base < NTOT; base += 1024) {
        int i = base + t;
        int vi = (i < NTOT) ? g_cnt[i] : 0;
#pragma unroll
        for (int o = 1; o < 32; o <<= 1) {
            int n = __shfl_up_sync(0xffffffffu, vi, o);
            if (lane >= o) vi += n;
        }
        if (lane == 31) wsum[wid] = vi;
        __syncthreads();
        if (wid == 0) {
            int s = wsum[lane];
#pragma unroll
            for (int o = 1; o < 32; o <<= 1) {
                int n = __shfl_up_sync(0xffffffffu, s, o);
                if (lane >= o) s += n;
            }
            wsum[lane] = s;
        }
        __syncthreads();
        int incl = vi + (wid ? wsum[wid - 1] : 0);
        int c = carryS;
        if (i < NTOT) g_rowptr[i + 1] = c + incl;
        int tot = wsum[31];
        __syncthreads();
        if (t == 0) carryS = c + tot;
        __syncthreads();
    }
}

__global__ void scatter_kernel(const int* __restrict__ lap_row,
                               const int* __restrict__ lap_col,
                               const float* __restrict__ lap_val) {
    int e = blockIdx.x * blockDim.x + threadIdx.x;
    if (e < NNZ) {
        int r = lap_row[e];
        int p = g_rowptr[r] + atomicAdd(&g_fill[r], 1);
        g_cols[p] = lap_col[e];
        g_vals[p] = lap_val[e];
    }
}

// ---------------- user MLP + scatter-update ----------------
__global__ void umlp_kernel(const float* __restrict__ feat,
                            const float* __restrict__ w1, const float* __restrict__ b1,
                            const float* __restrict__ w2, const float* __restrict__ b2) {
    __shared__ float h[32];
    __shared__ float f[4];
    int b = blockIdx.x, t = threadIdx.x;
    if (t < 4) f[t] = feat[b * 4 + t];
    __syncthreads();
    if (t < 32) {
        float s = b1[t];
#pragma unroll
        for (int i = 0; i < 4; i++) s = fmaf(f[i], w1[i * 32 + t], s);
        h[t] = s;
    }
    __syncthreads();
    float s = b2[t];
#pragma unroll
    for (int k = 0; k < 32; k++) s = fmaf(h[k], w2[k * 64 + t], s);
    g_umlp[b * 64 + t] = s;
}

__global__ void winner_kernel(const int* __restrict__ user_idx) {
    int i = threadIdx.x;  // 1 block of BATCH threads
    atomicMax(&g_winner[user_idx[i]], i);
}

__global__ void initE_kernel(const float* __restrict__ user_emb,
                             const float* __restrict__ item_emb,
                             const float* __restrict__ ratio_p) {
    int gid = blockIdx.x * blockDim.x + threadIdx.x;
    if (gid >= NTOT * 16) return;
    int node = gid >> 4, c = gid & 15;
    float4 v;
    if (node < N_USER) {
        v = reinterpret_cast<const float4*>(user_emb)[node * 16 + c];
        int w = g_winner[node];
        if (w >= 0) {
            float r = *ratio_p;
            float4 m = reinterpret_cast<const float4*>(g_umlp)[w * 16 + c];
            v.x = v.x * (1.0f - r) + m.x * r;
            v.y = v.y * (1.0f - r) + m.y * r;
            v.z = v.z * (1.0f - r) + m.z * r;
            v.w = v.w * (1.0f - r) + m.w * r;
        }
    } else {
        v = reinterpret_cast<const float4*>(item_emb)[(node - N_USER) * 16 + c];
    }
    reinterpret_cast<float4*>(g_E[0])[(size_t)node * 16 + c] = v;
    reinterpret_cast<float4*>(g_allE)[(size_t)node * 64 + c] = v;
}

// ---------------- fused layer: SpMM gather + dual GEMM + leaky + norm ----------------
__global__ void __launch_bounds__(256) layer_kernel(int parity,
                                                    const float* __restrict__ w1g,
                                                    const float* __restrict__ b1g,
                                                    const float* __restrict__ w2g,
                                                    const float* __restrict__ b2g,
                                                    int slice) {
    __shared__ __align__(16) float w1s[D * D];
    __shared__ __align__(16) float w2s[D * D];
    __shared__ __align__(16) float bsum[D];
    const float* __restrict__ Ein = g_E[parity];
    float* __restrict__ Eout = g_E[parity ^ 1];
    int tid = threadIdx.x;
    for (int i = tid; i < D * D / 4; i += 256) {
        reinterpret_cast<float4*>(w1s)[i] = reinterpret_cast<const float4*>(w1g)[i];
        reinterpret_cast<float4*>(w2s)[i] = reinterpret_cast<const float4*>(w2g)[i];
    }
    if (tid < D) bsum[tid] = b1g[tid] + b2g[tid];
    __syncthreads();

    int lane = tid & 31, warp = tid >> 5;
    int row0 = blockIdx.x * 32 + warp * 4;
    const float2* __restrict__ E2 = reinterpret_cast<const float2*>(Ein);

    float2 lie[4], lee[4];
#pragma unroll
    for (int rr = 0; rr < 4; rr++) {
        int row = row0 + rr;
        float a0 = 0.f, a1 = 0.f;
        float2 er = make_float2(0.f, 0.f);
        if (row < NTOT) {
            int s = g_rowptr[row], e = g_rowptr[row + 1];
            for (int b0 = s; b0 < e; b0 += 32) {
                int idx = b0 + lane;
                int c = 0; float v = 0.f;
                if (idx < e) { c = g_cols[idx]; v = g_vals[idx]; }
                int m = e - b0; if (m > 32) m = 32;
                for (int j = 0; j < m; j++) {
                    int cc = __shfl_sync(0xffffffffu, c, j);
                    float vv = __shfl_sync(0xffffffffu, v, j);
                    float2 ev = E2[(size_t)cc * 32 + lane];
                    a0 = fmaf(vv, ev.x, a0);
                    a1 = fmaf(vv, ev.y, a1);
                }
            }
            er = E2[(size_t)row * 32 + lane];
        }
        lie[rr] = make_float2(a0 + er.x, a1 + er.y);   // (L+I)E
        lee[rr] = make_float2(a0 * er.x, a1 * er.y);   // LE ∘ E
    }

    // dual GEMM: out[j] = sum_k lie[k]*w1[k][j] + lee[k]*w2[k][j] + b1[j]+b2[j]
    unsigned long long outp[4];
    {
        float2 bs = reinterpret_cast<const float2*>(bsum)[lane];
        unsigned long long bp = pack2(bs.x, bs.y);
#pragma unroll
        for (int rr = 0; rr < 4; rr++) outp[rr] = bp;
    }
    const unsigned long long* __restrict__ w1v = reinterpret_cast<const unsigned long long*>(w1s);
    const unsigned long long* __restrict__ w2v = reinterpret_cast<const unsigned long long*>(w2s);
#pragma unroll
    for (int k = 0; k < D; k++) {
        unsigned long long w1k = w1v[k * 32 + lane];
        unsigned long long w2k = w2v[k * 32 + lane];
        int src = k >> 1;
#pragma unroll
        for (int rr = 0; rr < 4; rr++) {
            float l = __shfl_sync(0xffffffffu, (k & 1) ? lie[rr].y : lie[rr].x, src);
            float g = __shfl_sync(0xffffffffu, (k & 1) ? lee[rr].y : lee[rr].x, src);
            outp[rr] = ffma2(pack_dup(l), w1k, outp[rr]);
            outp[rr] = ffma2(pack_dup(g), w2k, outp[rr]);
        }
    }

    float2* Eout2 = reinterpret_cast<float2*>(Eout);
    float2* allE2 = reinterpret_cast<float2*>(g_allE);
#pragma unroll
    for (int rr = 0; rr < 4; rr++) {
        int row = row0 + rr;
        if (row < NTOT) {
            float2 m = unpack2(outp[rr]);
            float2 a;
            a.x = m.x >= 0.f ? m.x : 0.2f * m.x;
            a.y = m.y >= 0.f ? m.y : 0.2f * m.y;
            Eout2[(size_t)row * 32 + lane] = a;          // unnormalized carries forward
            float ss = a.x * a.x + a.y * a.y;
#pragma unroll
            for (int o = 16; o > 0; o >>= 1) ss += __shfl_xor_sync(0xffffffffu, ss, o);
            float nrm = sqrtf(ss);
            float sc = 1.0f / fmaxf(nrm, 1e-12f);
            allE2[(size_t)row * 128 + slice * 32 + lane] = make_float2(a.x * sc, a.y * sc);
        }
    }
}

// ---------------- final gather ----------------
__global__ void out_kernel(const int* __restrict__ uidx,
                           const int* __restrict__ pidx,
                           const int* __restrict__ nidx,
                           float* __restrict__ out) {
    int g = blockIdx.x;
    int b = g & (BATCH - 1);
    int which = g >> 10;
    int row;
    if (which == 0) row = uidx[b];
    else if (which == 1) row = N_USER + pidx[b];
    else row = N_USER + nidx[b];
    const float4* src = reinterpret_cast<const float4*>(g_allE + (size_t)row * 256);
    float4* dst = reinterpret_cast<float4*>(out) + (size_t)g * 64;
    dst[threadIdx.x] = src[threadIdx.x];
}

// ---------------- launch ----------------
extern "C" void kernel_launch(void* const* d_in, const int* in_sizes, int n_in,
                              void* d_out, int out_size) {
    // Resolve input ordering at runtime:
    //  - reference-signature order puts user_feat (4096 elems) at slot 2
    //  - setup_inputs dict order puts lin1_w (128 elems) at slot 2
    int iUE, iIE, iUF, iL1W, iL1B, iL2W, iL2B, iW1, iB1, iW2, iB2, iLV, iR, iLR, iLC, iUI, iPI, iNI;
    if (n_in >= 18 && in_sizes[2] == 4096) {
        iUE = 0; iIE = 1; iUF = 2; iL1W = 3; iL1B = 4; iL2W = 5; iL2B = 6;
        iW1 = 7; iB1 = 8; iW2 = 9; iB2 = 10; iLV = 11; iR = 12; iLR = 13; iLC = 14;
        iUI = 15; iPI = 16; iNI = 17;
    } else {
        iUE = 0; iIE = 1; iL1W = 2; iL1B = 3; iL2W = 4; iL2B = 5;
        iW1 = 6; iB1 = 7; iW2 = 8; iB2 = 9; iLR = 10; iLC = 11; iLV = 12;
        iUI = 13; iUF = 14; iPI = 15; iNI = 16; iR = 17;
    }

    const float* user_emb = (const float*)d_in[iUE];
    const float* item_emb = (const float*)d_in[iIE];
    const float* user_feat = (const float*)d_in[iUF];
    const float* lin1_w = (const float*)d_in[iL1W];
    const float* lin1_b = (const float*)d_in[iL1B];
    const float* lin2_w = (const float*)d_in[iL2W];
    const float* lin2_b = (const float*)d_in[iL2B];
    const float* w1 = (const float*)d_in[iW1];
    const float* b1 = (const float*)d_in[iB1];
    const float* w2 = (const float*)d_in[iW2];
    const float* b2 = (const float*)d_in[iB2];
    const float* lap_val = (const float*)d_in[iLV];
    const float* ratio = (const float*)d_in[iR];
    const int* lap_row = (const int*)d_in[iLR];
    const int* lap_col = (const int*)d_in[iLC];
    const int* user_idx = (const int*)d_in[iUI];
    const int* pos_idx = (const int*)d_in[iPI];
    const int* neg_idx = (const int*)d_in[iNI];

    // CSR build (per call; structure is constant within a call)
    zero_kernel<<<(NTOT + 255) / 256, 256>>>();
    hist_kernel<<<(NNZ + 255) / 256, 256>>>(lap_row);
    scan_kernel<<<1, 1024>>>();
    scatter_kernel<<<(NNZ + 255) / 256, 256>>>(lap_row, lap_col, lap_val);

    // user MLP + last-wins scatter update + E0 / all_E slice 0
    umlp_kernel<<<BATCH, 64>>>(user_feat, lin1_w, lin1_b, lin2_w, lin2_b);
    winner_kernel<<<1, BATCH>>>(user_idx);
    initE_kernel<<<(NTOT * 16 + 255) / 256, 256>>>(user_emb, item_emb, ratio);

    // 3 fused graph-conv layers
    for (int k = 0; k < NLAY; k++) {
        layer_kernel<<<(NTOT + 31) / 32, 256>>>(k & 1,
                                                w1 + k * D * D, b1 + k * D,
                                                w2 + k * D * D, b2 + k * D,
                                                k + 1);
    }

    // gather (users[user_idx], items[pos_idx], items[neg_idx])
    out_kernel<<<3 * BATCH, 64>>>(user_idx, pos_idx, neg_idx, (float*)d_out);
}

// round 4
// speedup vs baseline: 1.2565x; 1.2565x over previous
#include <cuda_runtime.h>
#include <cuda_fp16.h>

#define N_USER 50000
#define N_ITEM 100000
#define NTOT   150000
#define D      64
#define NLAY   3
#define NNZ    2400000
#define BATCH  1024
#define SCANB  1024
#define NBLK   ((NTOT + SCANB - 1) / SCANB)   // 147
#define ASTRIDE 68                            // padded smem row stride (floats), conflict-free

// ---------------- scratch (static device globals; no allocation) ----------------
__device__ int      g_rowptr[NTOT + 1];
__device__ int      g_cnt[NTOT];
__device__ int      g_pos[NNZ];
__device__ int      g_bsum[NBLK + 16];
__device__ int      g_boff[NBLK + 16];
__device__ int      g_cols[NNZ];
__device__ float    g_vals[NNZ];
__device__ float    g_E[2][(size_t)NTOT * D];            // ping-pong fp32 (own-row reads)
__device__ unsigned g_Eh[2][(size_t)NTOT * 32];          // ping-pong fp16x2 (gather reads)
__device__ float    g_allE[(size_t)NTOT * 4 * D];        // [E0 | n1 | n2 | n3], row stride 256
__device__ float    g_umlp[BATCH * D];
__device__ int      g_winner[N_USER];

// ---------------- f32x2 helpers ----------------
__device__ __forceinline__ unsigned long long pack_dup(float a) {
    unsigned long long r;
    asm("mov.b64 %0, {%1, %1};" : "=l"(r) : "f"(a));
    return r;
}
__device__ __forceinline__ unsigned long long pack2(float x, float y) {
    unsigned long long r;
    asm("mov.b64 %0, {%1, %2};" : "=l"(r) : "f"(x), "f"(y));
    return r;
}
__device__ __forceinline__ float2 unpack2(unsigned long long v) {
    float2 r;
    asm("mov.b64 {%0, %1}, %2;" : "=f"(r.x), "=f"(r.y) : "l"(v));
    return r;
}
__device__ __forceinline__ unsigned long long ffma2(unsigned long long a,
                                                    unsigned long long b,
                                                    unsigned long long c) {
    unsigned long long d;
    asm("fma.rn.f32x2 %0, %1, %2, %3;" : "=l"(d) : "l"(a), "l"(b), "l"(c));
    return d;
}

// ---------------- CSR build ----------------
__global__ void zero_kernel() {
    int i = blockIdx.x * blockDim.x + threadIdx.x;
    if (i < NTOT) g_cnt[i] = 0;
    if (i < N_USER) g_winner[i] = -1;
}

// one atomic pass: histogram AND per-edge slot in one go
__global__ void histpos_kernel(const int* __restrict__ lap_row) {
    int e = blockIdx.x * blockDim.x + threadIdx.x;
    if (e < NNZ) g_pos[e] = atomicAdd(&g_cnt[lap_row[e]], 1);
}

__global__ void blockscan_kernel() {
    __shared__ int wsum[32];
    int t = threadIdx.x, lane = t & 31, wid = t >> 5;
    int i = blockIdx.x * SCANB + t;
    int v = (i < NTOT) ? g_cnt[i] : 0;
#pragma unroll
    for (int o = 1; o < 32; o <<= 1) {
        int n = __shfl_up_sync(0xffffffffu, v, o);
        if (lane >= o) v += n;
    }
    if (lane == 31) wsum[wid] = v;
    __syncthreads();
    if (wid == 0) {
        int s = wsum[lane];
#pragma unroll
        for (int o = 1; o < 32; o <<= 1) {
            int n = __shfl_up_sync(0xffffffffu, s, o);
            if (lane >= o) s += n;
        }
        wsum[lane] = s;
    }
    __syncthreads();
    int incl = v + (wid ? wsum[wid - 1] : 0);
    if (i < NTOT) g_cnt[i] = incl;
    if (t == SCANB - 1) g_bsum[blockIdx.x] = incl;
}

__global__ void topscan_kernel() {
    __shared__ int s[256];
    int t = threadIdx.x;
    int v = (t < NBLK) ? g_bsum[t] : 0;
    s[t] = v;
    __syncthreads();
#pragma unroll
    for (int o = 1; o < 256; o <<= 1) {
        int add = (t >= o) ? s[t - o] : 0;
        __syncthreads();
        s[t] += add;
        __syncthreads();
    }
    if (t < NBLK) g_boff[t] = s[t] - v;   // exclusive
}

__global__ void finalize_kernel() {
    int i = blockIdx.x * blockDim.x + threadIdx.x;
    if (i < NTOT) g_rowptr[i + 1] = g_cnt[i] + g_boff[i >> 10];
    if (i == 0) g_rowptr[0] = 0;
}

// no atomics: final slot = rowptr[r] + pos[e]
__global__ void place_kernel(const int* __restrict__ lap_row,
                             const int* __restrict__ lap_col,
                             const float* __restrict__ lap_val) {
    int e = blockIdx.x * blockDim.x + threadIdx.x;
    if (e < NNZ) {
        int r = lap_row[e];
        int p = g_rowptr[r] + g_pos[e];
        g_cols[p] = lap_col[e];
        g_vals[p] = lap_val[e];
    }
}

// ---------------- user MLP + scatter-update ----------------
__global__ void umlp_kernel(const float* __restrict__ feat,
                            const float* __restrict__ w1, const float* __restrict__ b1,
                            const float* __restrict__ w2, const float* __restrict__ b2) {
    __shared__ float h[32];
    __shared__ float f[4];
    int b = blockIdx.x, t = threadIdx.x;
    if (t < 4) f[t] = feat[b * 4 + t];
    __syncthreads();
    if (t < 32) {
        float s = b1[t];
#pragma unroll
        for (int i = 0; i < 4; i++) s = fmaf(f[i], w1[i * 32 + t], s);
        h[t] = s;
    }
    __syncthreads();
    float s = b2[t];
#pragma unroll
    for (int k = 0; k < 32; k++) s = fmaf(h[k], w2[k * 64 + t], s);
    g_umlp[b * 64 + t] = s;
}

__global__ void winner_kernel(const int* __restrict__ user_idx) {
    int i = threadIdx.x;
    atomicMax(&g_winner[user_idx[i]], i);
}

__global__ void initE_kernel(const float* __restrict__ user_emb,
                             const float* __restrict__ item_emb,
                             const float* __restrict__ ratio_p) {
    int gid = blockIdx.x * blockDim.x + threadIdx.x;
    if (gid >= NTOT * 16) return;
    int node = gid >> 4, c = gid & 15;
    float4 v;
    if (node < N_USER) {
        v = reinterpret_cast<const float4*>(user_emb)[node * 16 + c];
        int w = g_winner[node];
        if (w >= 0) {
            float r = *ratio_p;
            float4 m = reinterpret_cast<const float4*>(g_umlp)[w * 16 + c];
            v.x = v.x * (1.0f - r) + m.x * r;
            v.y = v.y * (1.0f - r) + m.y * r;
            v.z = v.z * (1.0f - r) + m.z * r;
            v.w = v.w * (1.0f - r) + m.w * r;
        }
    } else {
        v = reinterpret_cast<const float4*>(item_emb)[(node - N_USER) * 16 + c];
    }
    reinterpret_cast<float4*>(g_E[0])[(size_t)node * 16 + c] = v;
    reinterpret_cast<float4*>(g_allE)[(size_t)node * 64 + c] = v;
    __half2 h01 = __floats2half2_rn(v.x, v.y);
    __half2 h23 = __floats2half2_rn(v.z, v.w);
    uint2 hp;
    hp.x = *reinterpret_cast<unsigned*>(&h01);
    hp.y = *reinterpret_cast<unsigned*>(&h23);
    reinterpret_cast<uint2*>(g_Eh[0])[(size_t)node * 16 + c] = hp;
}

// ---------------- fused layer: SpMM (fp16 gather) + staged dual GEMM + leaky + norm ----------------
__global__ void __launch_bounds__(256) layer_kernel(int parity,
                                                    const float* __restrict__ w1g,
                                                    const float* __restrict__ b1g,
                                                    const float* __restrict__ w2g,
                                                    const float* __restrict__ b2g,
                                                    int slice, int last) {
    __shared__ __align__(16) float wbuf[D * D];                 // 16 KB, reused w1 then w2
    __shared__ __align__(16) float lie_s[32 * ASTRIDE];          // 8.7 KB
    __shared__ __align__(16) float lee_s[32 * ASTRIDE];          // 8.7 KB

    const float*    __restrict__ Ein  = g_E[parity];
    float*          __restrict__ Eout = g_E[parity ^ 1];
    const unsigned* __restrict__ Ehin = g_Eh[parity];
    unsigned*       __restrict__ Ehout = g_Eh[parity ^ 1];

    int tid = threadIdx.x;
    int lane = tid & 31, warp = tid >> 5;
    int rbase = blockIdx.x * 32;

    // stage w1 while SpMM runs
    for (int i = tid; i < D * D / 4; i += 256)
        reinterpret_cast<float4*>(wbuf)[i] = reinterpret_cast<const float4*>(w1g)[i];

    // ---- phase 1: SpMM, warp handles 4 rows; lane owns cols {2*lane, 2*lane+1}
    const float2* __restrict__ E2 = reinterpret_cast<const float2*>(Ein);
#pragma unroll
    for (int rr = 0; rr < 4; rr++) {
        int lrow = warp * 4 + rr;
        int row = rbase + lrow;
        float a0 = 0.f, a1 = 0.f;
        float2 er = make_float2(0.f, 0.f);
        if (row < NTOT) {
            int s = g_rowptr[row], e = g_rowptr[row + 1];
            for (int b0 = s; b0 < e; b0 += 32) {
                int idx = b0 + lane;
                int c = 0; float v = 0.f;
                if (idx < e) { c = g_cols[idx]; v = g_vals[idx]; }
                int m = e - b0; if (m > 32) m = 32;
                for (int j = 0; j < m; j++) {
                    int cc = __shfl_sync(0xffffffffu, c, j);
                    float vv = __shfl_sync(0xffffffffu, v, j);
                    unsigned hraw = Ehin[(size_t)cc * 32 + lane];
                    float2 ev = __half22float2(*reinterpret_cast<__half2*>(&hraw));
                    a0 = fmaf(vv, ev.x, a0);
                    a1 = fmaf(vv, ev.y, a1);
                }
            }
            er = E2[(size_t)row * 32 + lane];
        }
        float2* dl = reinterpret_cast<float2*>(&lie_s[lrow * ASTRIDE + 2 * lane]);
        float2* dg = reinterpret_cast<float2*>(&lee_s[lrow * ASTRIDE + 2 * lane]);
        *dl = make_float2(a0 + er.x, a1 + er.y);   // (L+I)E
        *dg = make_float2(a0 * er.x, a1 * er.y);   // LE ∘ E
    }
    __syncthreads();

    // ---- phase 2: block GEMM. thread -> rows {2*rowg, 2*rowg+1}, cols 4*colg..+3
    int rowg = tid >> 4, colg = tid & 15;
    int r0 = 2 * rowg, r1 = r0 + 1;
    int c0 = 4 * colg;

    unsigned long long acc0a, acc0b, acc1a, acc1b;
    {
        float4 bv1 = reinterpret_cast<const float4*>(b1g)[colg];
        float4 bv2 = reinterpret_cast<const float4*>(b2g)[colg];
        acc0a = pack2(bv1.x + bv2.x, bv1.y + bv2.y);
        acc0b = pack2(bv1.z + bv2.z, bv1.w + bv2.w);
        acc1a = acc0a; acc1b = acc0b;
    }

#pragma unroll 4
    for (int k0 = 0; k0 < D; k0 += 4) {
        float4 aA = *reinterpret_cast<const float4*>(&lie_s[r0 * ASTRIDE + k0]);
        float4 aB = *reinterpret_cast<const float4*>(&lie_s[r1 * ASTRIDE + k0]);
#pragma unroll
        for (int kk = 0; kk < 4; kk++) {
            float4 wv = *reinterpret_cast<const float4*>(&wbuf[(k0 + kk) * D + c0]);
            unsigned long long wlo = pack2(wv.x, wv.y);
            unsigned long long whi = pack2(wv.z, wv.w);
            float aAk = (&aA.x)[kk];
            float aBk = (&aB.x)[kk];
            unsigned long long dA = pack_dup(aAk);
            unsigned long long dB = pack_dup(aBk);
            acc0a = ffma2(dA, wlo, acc0a);
            acc0b = ffma2(dA, whi, acc0b);
            acc1a = ffma2(dB, wlo, acc1a);
            acc1b = ffma2(dB, whi, acc1b);
        }
    }
    __syncthreads();

    // reload weight buffer with w2
    for (int i = tid; i < D * D / 4; i += 256)
        reinterpret_cast<float4*>(wbuf)[i] = reinterpret_cast<const float4*>(w2g)[i];
    __syncthreads();

#pragma unroll 4
    for (int k0 = 0; k0 < D; k0 += 4) {
        float4 aA = *reinterpret_cast<const float4*>(&lee_s[r0 * ASTRIDE + k0]);
        float4 aB = *reinterpret_cast<const float4*>(&lee_s[r1 * ASTRIDE + k0]);
#pragma unroll
        for (int kk = 0; kk < 4; kk++) {
            float4 wv = *reinterpret_cast<const float4*>(&wbuf[(k0 + kk) * D + c0]);
            unsigned long long wlo = pack2(wv.x, wv.y);
            unsigned long long whi = pack2(wv.z, wv.w);
            float aAk = (&aA.x)[kk];
            float aBk = (&aB.x)[kk];
            unsigned long long dA = pack_dup(aAk);
            unsigned long long dB = pack_dup(aBk);
            acc0a = ffma2(dA, wlo, acc0a);
            acc0b = ffma2(dA, whi, acc0b);
            acc1a = ffma2(dB, wlo, acc1a);
            acc1b = ffma2(dB, whi, acc1b);
        }
    }

    // ---- epilogue: leaky relu, row norm (reduce over 16 threads sharing rowg), stores
    float2 o0a = unpack2(acc0a), o0b = unpack2(acc0b);
    float2 o1a = unpack2(acc1a), o1b = unpack2(acc1b);
    o0a.x = o0a.x >= 0.f ? o0a.x : 0.2f * o0a.x;
    o0a.y = o0a.y >= 0.f ? o0a.y : 0.2f * o0a.y;
    o0b.x = o0b.x >= 0.f ? o0b.x : 0.2f * o0b.x;
    o0b.y = o0b.y >= 0.f ? o0b.y : 0.2f * o0b.y;
    o1a.x = o1a.x >= 0.f ? o1a.x : 0.2f * o1a.x;
    o1a.y = o1a.y >= 0.f ? o1a.y : 0.2f * o1a.y;
    o1b.x = o1b.x >= 0.f ? o1b.x : 0.2f * o1b.x;
    o1b.y = o1b.y >= 0.f ? o1b.y : 0.2f * o1b.y;

    float ss0 = o0a.x * o0a.x + o0a.y * o0a.y + o0b.x * o0b.x + o0b.y * o0b.y;
    float ss1 = o1a.x * o1a.x + o1a.y * o1a.y + o1b.x * o1b.x + o1b.y * o1b.y;
#pragma unroll
    for (int o = 8; o > 0; o >>= 1) {
        ss0 += __shfl_xor_sync(0xffffffffu, ss0, o);
        ss1 += __shfl_xor_sync(0xffffffffu, ss1, o);
    }
    float sc0 = 1.0f / fmaxf(sqrtf(ss0), 1e-12f);
    float sc1 = 1.0f / fmaxf(sqrtf(ss1), 1e-12f);

    int grow0 = rbase + r0, grow1 = rbase + r1;
    float4* EoutV = reinterpret_cast<float4*>(Eout);
    uint2* EhV = reinterpret_cast<uint2*>(Ehout);
    float4* allEV = reinterpret_cast<float4*>(g_allE);

    if (grow0 < NTOT) {
        if (!last) {
            float4 w = make_float4(o0a.x, o0a.y, o0b.x, o0b.y);
            EoutV[(size_t)grow0 * 16 + colg] = w;
            __half2 h01 = __floats2half2_rn(w.x, w.y);
            __half2 h23 = __floats2half2_rn(w.z, w.w);
            uint2 hp;
            hp.x = *reinterpret_cast<unsigned*>(&h01);
            hp.y = *reinterpret_cast<unsigned*>(&h23);
            EhV[(size_t)grow0 * 16 + colg] = hp;
        }
        allEV[(size_t)grow0 * 64 + slice * 16 + colg] =
            make_float4(o0a.x * sc0, o0a.y * sc0, o0b.x * sc0, o0b.y * sc0);
    }
    if (grow1 < NTOT) {
        if (!last) {
            float4 w = make_float4(o1a.x, o1a.y, o1b.x, o1b.y);
            EoutV[(size_t)grow1 * 16 + colg] = w;
            __half2 h01 = __floats2half2_rn(w.x, w.y);
            __half2 h23 = __floats2half2_rn(w.z, w.w);
            uint2 hp;
            hp.x = *reinterpret_cast<unsigned*>(&h01);
            hp.y = *reinterpret_cast<unsigned*>(&h23);
            EhV[(size_t)grow1 * 16 + colg] = hp;
        }
        allEV[(size_t)grow1 * 64 + slice * 16 + colg] =
            make_float4(o1a.x * sc1, o1a.y * sc1, o1b.x * sc1, o1b.y * sc1);
    }
}

// ---------------- final gather ----------------
__global__ void out_kernel(const int* __restrict__ uidx,
                           const int* __restrict__ pidx,
                           const int* __restrict__ nidx,
                           float* __restrict__ out) {
    int g = blockIdx.x;
    int b = g & (BATCH - 1);
    int which = g >> 10;
    int row;
    if (which == 0) row = uidx[b];
    else if (which == 1) row = N_USER + pidx[b];
    else row = N_USER + nidx[b];
    const float4* src = reinterpret_cast<const float4*>(g_allE + (size_t)row * 256);
    float4* dst = reinterpret_cast<float4*>(out) + (size_t)g * 64;
    dst[threadIdx.x] = src[threadIdx.x];
}

// ---------------- launch ----------------
extern "C" void kernel_launch(void* const* d_in, const int* in_sizes, int n_in,
                              void* d_out, int out_size) {
    int iUE, iIE, iUF, iL1W, iL1B, iL2W, iL2B, iW1, iB1, iW2, iB2, iLV, iR, iLR, iLC, iUI, iPI, iNI;
    if (n_in >= 18 && in_sizes[2] == 4096) {
        iUE = 0; iIE = 1; iUF = 2; iL1W = 3; iL1B = 4; iL2W = 5; iL2B = 6;
        iW1 = 7; iB1 = 8; iW2 = 9; iB2 = 10; iLV = 11; iR = 12; iLR = 13; iLC = 14;
        iUI = 15; iPI = 16; iNI = 17;
    } else {
        iUE = 0; iIE = 1; iL1W = 2; iL1B = 3; iL2W = 4; iL2B = 5;
        iW1 = 6; iB1 = 7; iW2 = 8; iB2 = 9; iLR = 10; iLC = 11; iLV = 12;
        iUI = 13; iUF = 14; iPI = 15; iNI = 16; iR = 17;
    }

    const float* user_emb = (const float*)d_in[iUE];
    const float* item_emb = (const float*)d_in[iIE];
    const float* user_feat = (const float*)d_in[iUF];
    const float* lin1_w = (const float*)d_in[iL1W];
    const float* lin1_b = (const float*)d_in[iL1B];
    const float* lin2_w = (const float*)d_in[iL2W];
    const float* lin2_b = (const float*)d_in[iL2B];
    const float* w1 = (const float*)d_in[iW1];
    const float* b1 = (const float*)d_in[iB1];
    const float* w2 = (const float*)d_in[iW2];
    const float* b2 = (const float*)d_in[iB2];
    const float* lap_val = (const float*)d_in[iLV];
    const float* ratio = (const float*)d_in[iR];
    const int* lap_row = (const int*)d_in[iLR];
    const int* lap_col = (const int*)d_in[iLC];
    const int* user_idx = (const int*)d_in[iUI];
    const int* pos_idx = (const int*)d_in[iPI];
    const int* neg_idx = (const int*)d_in[iNI];

    // CSR build: single atomic pass + parallel scan + atomic-free place
    zero_kernel<<<(NTOT + 255) / 256, 256>>>();
    histpos_kernel<<<(NNZ + 255) / 256, 256>>>(lap_row);
    blockscan_kernel<<<NBLK, SCANB>>>();
    topscan_kernel<<<1, 256>>>();
    finalize_kernel<<<(NTOT + 255) / 256, 256>>>();
    place_kernel<<<(NNZ + 255) / 256, 256>>>(lap_row, lap_col, lap_val);

    // user MLP + last-wins scatter update + E0 (fp32 + fp16 copies) + all_E slice 0
    umlp_kernel<<<BATCH, 64>>>(user_feat, lin1_w, lin1_b, lin2_w, lin2_b);
    winner_kernel<<<1, BATCH>>>(user_idx);
    initE_kernel<<<(NTOT * 16 + 255) / 256, 256>>>(user_emb, item_emb, ratio);

    // 3 fused graph-conv layers
    for (int k = 0; k < NLAY; k++) {
        layer_kernel<<<(NTOT + 31) / 32, 256>>>(k & 1,
                                                w1 + k * D * D, b1 + k * D,
                                                w2 + k * D * D, b2 + k * D,
                                                k + 1, k == NLAY - 1);
    }

    out_kernel<<<3 * BATCH, 64>>>(user_idx, pos_idx, neg_idx, (float*)d_out);
}